// round 13
// baseline (speedup 1.0000x reference)
#include <cuda_runtime.h>
#include <cstdint>

namespace {
constexpr int K     = 9;
constexpr int NB    = 64;
constexpr int NH    = 32;
constexpr int NW    = 32;
constexpr int NCELL = NH * NW;       // 1024
constexpr int NT    = 50;
constexpr int NLAB  = 2 * K + 3;     // 21
constexpr int CH    = 2 * K + 2;     // 20
constexpr float THR = 80.0f;
constexpr float IMW = 640.0f;
constexpr float IMH = 480.0f;
constexpr float SIL = 0.6f;
constexpr float OBJ = 5.0f;
constexpr int   TPB  = 1024;         // 2 threads per cell (paired lanes)
constexpr int   NBLK = 128;          // 128 CTAs, 1/SM, single wave
constexpr float CELLW = IMW / NW;    // 20 px
constexpr float CELLH = IMH / NH;    // 15 px
constexpr float THR2  = THR * THR;   // 6400
constexpr float GATE  = 40.0f;       // silent needs >=5 corners within 40px
constexpr float GATE2 = GATE * GATE;
constexpr unsigned FULL = 0xffffffffu;
}

__device__ float        g_partials[NBLK];
__device__ unsigned int g_count = 0;

__device__ __forceinline__ uint32_t smem_u32(const void* p) {
    uint32_t a;
    asm("{ .reg .u64 t; cvta.to.shared.u64 t, %1; cvt.u32.u64 %0, t; }"
        : "=r"(a) : "l"(p));
    return a;
}

// d2 = |g - p|^2 via packed f32x2 (g from smem, negp = packed(-px,-py))
__device__ __forceinline__ float d2_packed(uint32_t addr, uint64_t negp) {
    uint64_t g, d, s;
    asm volatile("ld.shared.b64 %0, [%1];" : "=l"(g) : "r"(addr));
    asm("add.rn.f32x2 %0, %1, %2;" : "=l"(d) : "l"(g), "l"(negp));
    asm("mul.rn.f32x2 %0, %1, %2;" : "=l"(s) : "l"(d), "l"(d));
    uint32_t lo, hi;
    asm("mov.b64 {%0, %1}, %2;" : "=r"(lo), "=r"(hi) : "l"(s));
    return __uint_as_float(lo) + __uint_as_float(hi);
}

__global__ __launch_bounds__(TPB, 1) void region_loss_kernel(
    const float* __restrict__ out,
    const float* __restrict__ tgt,
    const int*   __restrict__ epoch_p,
    float*       __restrict__ loss)
{
    __shared__ float2 sXY[NT][10];                 // col 9 = poison pad (1e30)
    __shared__ float swarp[TPB / 32];

    const int bid  = blockIdx.x;
    const int b    = bid >> 1;
    const int tid  = threadIdx.x;
    const int lane = tid & 31;
    const int sub  = lane >> 4;                    // 0: corners 0-4, 1: corners 5-8(+pad)
    const int wid  = tid >> 5;                     // warp covers 16 cells
    const int cell = ((bid & 1) << 9) | (wid << 4) | (lane & 15);
    const int wbase = cell & ~15;
    const int kbase = sub * 5;

    // ---- 1) STAGING loads first (earliest L1tex queue slots -> early barrier)
    const float* tb = tgt + (size_t)b * (NT * NLAB);
    const bool do_stage = (tid < NT * 2 * K);
    int st = 0, sc = 0;
    float stg = 0.0f;
    if (do_stage) {
        st = tid / (2 * K); sc = tid - st * (2 * K);
        stg = tb[st * NLAB + 1 + sc];
    }
    const int epoch = epoch_p ? __ldg(epoch_p) : 20;

    // ---- 2) channel loads after (latency overlaps post-barrier compute)
    const float* ob = out + (size_t)(b * CH) * NCELL + cell;
    float rx[5], ry[5];
    #pragma unroll
    for (int k = 0; k < 5; k++) {
        rx[k] = ob[(sub * 10 + 2 * k) * NCELL];
        ry[k] = ob[(sub * 10 + 2 * k + 1) * NCELL];
    }

    if (do_stage) {
        float* dst = (float*)&sXY[st][sc >> 1];
        dst[sc & 1] = stg * ((sc & 1) ? IMH : IMW);
    }
    // poison pad column: sub1's 5th corner auto-yields d2=Inf (>= all gates)
    if (tid >= NT * 2 * K && tid < NT * 2 * K + NT)
        sXY[tid - NT * 2 * K][9] = make_float2(1e30f, 1e30f);
    __syncthreads();

    const uint32_t sb = smem_u32(&sXY[0][0]);

    // ---- 3) lane-parallel target metadata (lane t owns target t)
    float2 c0l = sXY[lane][0];
    float tby0 = c0l.y, tby1 = c0l.y;
    #pragma unroll
    for (int k = 1; k < K; k++) {
        float y = sXY[lane][k].y;
        tby0 = fminf(tby0, y); tby1 = fmaxf(tby1, y);
    }
    unsigned inv0 = ~__ballot_sync(FULL, c0l.x != 0.0f);
    bool v2 = (lane + 32 < NT) && (sXY[lane + 32][0].x != 0.0f);
    unsigned inv1 = ~__ballot_sync(FULL, v2);
    const int nv = inv0 ? (__ffs(inv0) - 1) : (31 + __ffs(inv1));

    int gi0l = (int)floorf(c0l.x * (1.0f / CELLW));
    int gj0l = (int)floorf(c0l.y * (1.0f / CELLH));
    int cellv = (gi0l >= 0 && gi0l < NW && gj0l >= 0 && gj0l < NH)
                    ? gj0l * NW + gi0l : -1;
    cellv = (lane < nv) ? cellv : -1;
    unsigned hitm = __ballot_sync(FULL, (cellv >= wbase) && (cellv < wbase + 16));
    int thit = -1;
    for (unsigned hm = hitm; hm; hm &= hm - 1) {   // ascending t: last wins
        int t  = __ffs(hm) - 1;
        int sct = __shfl_sync(FULL, cellv, t);
        thit = (sct == cell) ? t : thit;
    }

    // ---- 4) predictions: packed (-px,-py) per corner + warp y-bbox
    const bool do_conf = epoch > 15;
    const float i_f = (float)(cell & (NW - 1));
    const float j_f = (float)(cell >> 5);
    if (!sub) {
        rx[0] = 1.0f / (1.0f + __expf(-rx[0]));
        ry[0] = 1.0f / (1.0f + __expf(-ry[0]));
    }
    float confp = 1.0f / (1.0f + __expf(-__shfl_xor_sync(FULL, rx[4], 16)));

    uint64_t negp[5];
    float wminy = 1e30f, wmaxy = -1e30f;
    #pragma unroll
    for (int k = 0; k < 5; k++) {
        float pxk = (rx[k] + i_f) * CELLW;
        float pyk = (ry[k] + j_f) * CELLH;
        wminy = fminf(wminy, pyk); wmaxy = fmaxf(wmaxy, pyk);
        asm("mov.b64 %0, {%1, %2};" : "=l"(negp[k])
            : "r"(__float_as_uint(-pxk)), "r"(__float_as_uint(-pyk)));
    }
    #pragma unroll
    for (int o = 16; o > 0; o >>= 1) {
        wminy = fminf(wminy, __shfl_xor_sync(FULL, wminy, o));
        wmaxy = fmaxf(wmaxy, __shfl_xor_sync(FULL, wmaxy, o));
    }

    // exact y-prune: hot needs a corner within 40px => y-bboxes within 40px
    bool poss = (lane < nv) && (tby0 - wmaxy < GATE) && (wminy - tby1 < GATE);
    unsigned possm = __ballot_sync(FULL, poss);    // warp-uniform

    const float inv_denK = (1.0f / (float)K) / (__expf(2.0f) - 1.0f + 1e-5f);

    // ---- 5) sparse silent loop over surviving targets (nibble-batched)
    bool silent = false;
    unsigned pm = possm;
    while (pm) {
        unsigned word = 0;
        uint64_t tmap = 0;                         // slot -> t (uniform)
        int slot = 0;
        do {
            int t = __ffs(pm) - 1; pm &= pm - 1;
            uint32_t rowa = sb + (unsigned)t * 80u + (unsigned)kbase * 8u;
            unsigned cnt = 0;
            #pragma unroll
            for (int k = 0; k < 5; k++)
                cnt += (d2_packed(rowa + 8u * k, negp[k]) < GATE2);
            word |= cnt << (4 * slot);
            tmap |= (uint64_t)(unsigned)t << (8 * slot);
            slot++;
        } while (pm && slot < 8);
        unsigned sum = word + __shfl_xor_sync(FULL, word, 16);  // nibbles <= 10
        unsigned smask = (slot == 8) ? 0x88888888u
                        : (((1u << (4 * slot)) - 1u) & 0x88888888u);
        unsigned hot = ((sum + 0x33333333u) & 0x88888888u) & smask;
        unsigned un = __reduce_or_sync(FULL, hot);
        while (un) {                                            // rare, converged
            int p  = __ffs(un) - 1; un &= un - 1;
            int t  = (int)((tmap >> (8 * (p >> 2))) & 0xffu);
            uint32_t rowa = sb + (unsigned)t * 80u + (unsigned)kbase * 8u;
            float acc = 0.0f;
            #pragma unroll
            for (int k = 0; k < 5; k++) {
                float d2 = d2_packed(rowa + 8u * k, negp[k]);
                float cc = __expf(2.0f - sqrtf(d2) * (2.0f / THR)) - 1.0f;
                acc += (d2 < THR2) ? cc : 0.0f;
            }
            acc += __shfl_xor_sync(FULL, acc, 16);
            silent |= ((hot >> p) & 1u) && (acc * inv_denK > SIL);
        }
    }

    // ---- 5b) rare general path for targets t in [32, nv)
    for (int t = 32; t < nv; t++) {
        float2 c0 = sXY[t][0];
        int gi = (int)floorf(c0.x * (1.0f / CELLW));
        int gj = (int)floorf(c0.y * (1.0f / CELLH));
        int sct = (gi >= 0 && gi < NW && gj >= 0 && gj < NH) ? gj * NW + gi : -1;
        thit = (sct == cell) ? t : thit;
        uint32_t rowa = sb + (unsigned)t * 80u + (unsigned)kbase * 8u;
        unsigned cnt = 0;
        #pragma unroll
        for (int k = 0; k < 5; k++)
            cnt += (d2_packed(rowa + 8u * k, negp[k]) < GATE2);
        cnt += __shfl_xor_sync(FULL, cnt, 16);
        bool hot = (cnt >= 5);
        if (__any_sync(FULL, hot)) {
            float acc = 0.0f;
            #pragma unroll
            for (int k = 0; k < 5; k++) {
                float d2 = d2_packed(rowa + 8u * k, negp[k]);
                float cc = __expf(2.0f - sqrtf(d2) * (2.0f / THR)) - 1.0f;
                acc += (d2 < THR2) ? cc : 0.0f;
            }
            acc += __shfl_xor_sync(FULL, acc, 16);
            silent |= hot && (acc * inv_denK > SIL);
        }
    }

    // ---- 6) per-cell loss. Hit epilogue WARP-UNIFORM (converged shuffles).
    float lcl = 0.0f;
    if (__any_sync(FULL, thit >= 0)) {
        const int th = (thit >= 0) ? thit : 0;
        float2 g0 = sXY[th][0];
        float gx0 = floorf(g0.x * (1.0f / CELLW));
        float gy0 = floorf(g0.y * (1.0f / CELLH));
        uint32_t rowa = sb + (unsigned)th * 80u + (unsigned)kbase * 8u;
        float closs = 0.0f, acc = 0.0f;
        #pragma unroll
        for (int k = 0; k < 5; k++) {
            float2 gc = sXY[th][kbase + k];
            float ex = rx[k] - (gc.x * (1.0f / CELLW) - gx0);
            float ey = ry[k] - (gc.y * (1.0f / CELLH) - gy0);
            // SEL (not *0) so pad-column magnitude can never propagate
            closs += (sub && k == 4) ? 0.0f : 0.5f * (ex * ex + ey * ey);
            float d2 = d2_packed(rowa + 8u * k, negp[k]);
            float cc = __expf(2.0f - sqrtf(d2) * (2.0f / THR)) - 1.0f;
            acc += (d2 < THR2) ? cc : 0.0f;
        }
        acc += __shfl_xor_sync(FULL, acc, 16);          // converged pair combine
        if (thit >= 0) {
            lcl += closs;
            if (do_conf && !sub) {
                float e = confp - acc * inv_denK;
                lcl += 0.5f * OBJ * e * e;
            }
        }
    }
    if (thit < 0 && do_conf && !sub)
        lcl += silent ? 0.0f : 0.5f * confp * confp;    // NOOBJ, tconf = 0

    // ---- 7) warp reduce -> swarp -> ONE barrier; only warp 0 continues.
    #pragma unroll
    for (int o = 16; o > 0; o >>= 1)
        lcl += __shfl_xor_sync(FULL, lcl, o);
    if (lane == 0) swarp[wid] = lcl;
    __syncthreads();
    if (tid >= 32) return;            // 31 warps exit; no tail barrier

    float v = swarp[tid];             // 32 warp partials
    #pragma unroll
    for (int o = 16; o > 0; o >>= 1)
        v += __shfl_xor_sync(FULL, v, o);
    int lastf = 0;
    if (tid == 0) {
        g_partials[bid] = v;
        __threadfence();
        lastf = (atomicAdd(&g_count, 1) == NBLK - 1) ? 1 : 0;
    }
    lastf = __shfl_sync(FULL, lastf, 0);
    if (lastf) {                      // last CTA's warp 0 does the final sum
        float s = g_partials[tid]      + g_partials[tid + 32]
                + g_partials[tid + 64] + g_partials[tid + 96];
        #pragma unroll
        for (int o = 16; o > 0; o >>= 1)
            s += __shfl_xor_sync(FULL, s, o);
        if (tid == 0) {
            loss[0] = s;
            g_count = 0;              // reset for next graph replay
        }
    }
}

extern "C" void kernel_launch(void* const* d_in, const int* in_sizes, int n_in,
                              void* d_out, int out_size)
{
    const float* output = (const float*)d_in[0];
    const float* target = (const float*)d_in[1];
    const int*   epoch  = (n_in > 2) ? (const int*)d_in[2] : nullptr;
    float* loss = (float*)d_out;

    region_loss_kernel<<<NBLK, TPB>>>(output, target, epoch, loss);
    (void)in_sizes; (void)out_size;
}